// round 12
// baseline (speedup 1.0000x reference)
#include <cuda_runtime.h>
#include <cstdint>

#define AREAS   10
#define NPA     192
#define CDIM    128
#define NDIM    1920
#define MROWS   32768
#define OUTC    1280
#define CHUNK_M 4096
#define NCHUNK  (MROWS / CHUNK_M)     // 8
#define KT      12
#define PR      4
#define MB_N    (CHUNK_M / 128)       // 32
#define NBUF    2

#define SROW_P  1924

#define XG_BUF_F ((size_t)MB_N * AREAS * KT * 2048)
__device__ float g_xg[NBUF * XG_BUF_F];
__device__ float g_Wt[AREAS * KT * 128 * 16];   // [a][kt][n][kr][i]
__device__ int   g_src[NDIM];
__device__ int   g_gperm[NDIM];

__device__ __forceinline__ float cvt_tf32(float v) {
    uint32_t u;
    asm("cvt.rna.tf32.f32 %0, %1;" : "=r"(u) : "f"(v));
    return __uint_as_float(u);
}

#define CP_ASYNC16(dst, src) \
    asm volatile("cp.async.cg.shared.global [%0], [%1], 16;" :: "r"(dst), "l"(src))
#define CP_COMMIT() asm volatile("cp.async.commit_group;" ::: "memory")
#define CP_WAIT0()  asm volatile("cp.async.wait_group 0;" ::: "memory")

// ---------------------------------------------------------------------------
__global__ void setup_src_kernel(const int* __restrict__ nr) {
    const int warp = threadIdx.x >> 5, lane = threadIdx.x & 31;
    if (warp < AREAS) {
        int cnt = 0;
        for (int base = 0; base < NDIM; base += 32) {
            const int n = base + lane;
            const bool m = (nr[n] == warp);
            const unsigned bal = __ballot_sync(0xffffffffu, m);
            if (m) g_src[warp * NPA + cnt + __popc(bal & ((1u << lane) - 1u))] = n;
            cnt += __popc(bal);
        }
    }
}

__global__ void gperm_kernel() {
    int q = blockIdx.x * 256 + threadIdx.x;
    if (q < NDIM) {
        int i   = q & 3;
        int kr  = (q >> 2) & 3;
        int akt = q >> 4;
        int a = akt / KT, kt = akt % KT;
        g_gperm[q] = g_src[a * NPA + kt * 16 + kr + 4 * i];
    }
}

__global__ void wcvt_kernel(const float* __restrict__ W) {
    int o = blockIdx.x * 256 + threadIdx.x;
    if (o < AREAS * KT * 128 * 16) {
        int i  = o & 3;
        int kr = (o >> 2) & 3;
        int n  = (o >> 4) & 127;
        int kt = (o >> 11) % KT;
        int a  = o / (KT * 128 * 16);
        int k  = kt * 16 + kr + 4 * i;
        g_Wt[o] = cvt_tf32(W[(a * NPA + k) * CDIM + n]);
    }
}

// ---------------------------------------------------------------------------
// Permute 4 rows/block, 4 CTAs/SM. lane=(sub,row,kr): each half-warp writes
// one slab's contiguous 256B run.
// ---------------------------------------------------------------------------
__global__ __launch_bounds__(256, 4)
void permute_kernel(const float* __restrict__ x, int chunk_row0, int buf) {
    __shared__ float srow[PR * SROW_P];
    const int tid  = threadIdx.x;
    const int warp = tid >> 5, lane = tid & 31;
    const int r0   = blockIdx.x * PR;
    const int mb   = r0 >> 7;
    const int rloc = r0 & 127;

    const float4* x4 = (const float4*)(x + ((size_t)chunk_row0 + r0) * NDIM);
    for (int i = tid; i < PR * NDIM / 4; i += 256) {
        int row = i / 480, c4 = i % 480;
        *(float4*)(srow + row * SROW_P + c4 * 4) = x4[i];
    }
    __syncthreads();

    const int sub = lane >> 4;
    const int row = (lane >> 2) & 3;
    const int kr  = lane & 3;
    const float* sr = srow + row * SROW_P;
    float* xgb = g_xg + (size_t)buf * XG_BUF_F;
    const size_t slab0 = (size_t)mb * (AREAS * KT);
    const int dst_off = (rloc + row) * 16 + kr * 4;

    #pragma unroll
    for (int it = 0; it < 8; it++) {
        const int k = 2 * it + sub;
        if (k < 15) {
            const int akt = warp + k * 8;     // 8 warps x 15 = 120 slabs
            const int4 g = *(const int4*)(g_gperm + (akt * 4 + kr) * 4);
            float4 v;
            v.x = cvt_tf32(sr[g.x]);
            v.y = cvt_tf32(sr[g.y]);
            v.z = cvt_tf32(sr[g.z]);
            v.w = cvt_tf32(sr[g.w]);
            *(float4*)(xgb + (slab0 + akt) * 2048 + dst_off) = v;
        }
    }
}

// ---------------------------------------------------------------------------
// GEMM: block = (mb, nh, a) computing 128x64. 8 warps as 4Mx2N, warp 32x32.
// 48KB B half-slab in SMEM, 3 CTAs/SM, A from L2 with register prefetch.
// ---------------------------------------------------------------------------
#define BH_F 12288                    // 12*64*16 floats
#define SMEM_BYTES (BH_F * 4)         // 49152

__global__ __launch_bounds__(256, 3)
void gemm_kernel(const float* __restrict__ bias, float* __restrict__ out,
                 int chunk_row0, int buf) {
    extern __shared__ float Bs[];
    const int a    = blockIdx.y;
    const int mb   = blockIdx.x >> 1;
    const int nh   = blockIdx.x & 1;
    const int tid  = threadIdx.x;
    const int warp = tid >> 5, lane = tid & 31;
    const int wm = warp >> 1;                 // 0..3
    const int wn = warp & 1;                  // 0..1
    const int qr = lane >> 2;
    const int kr = lane & 3;

    // B half-slab: src (a,kt,n=nh*64+nn,kr,i); dst contiguous
    const float* Wb = g_Wt + (size_t)a * (KT * 2048) + nh * 1024;
    #pragma unroll
    for (int s = 0; s < 12; s++) {
        int i = tid + s * 256;                // 3072 float4
        int kt = i >> 8, rem = i & 255;
        uint32_t dst = (uint32_t)__cvta_generic_to_shared(Bs + i * 4);
        CP_ASYNC16(dst, Wb + kt * 2048 + rem * 4);
    }
    CP_COMMIT();

    const int roff[2] = { wm * 32 + qr, wm * 32 + 8 + qr };
    const float* Ag = g_xg + (size_t)buf * XG_BUF_F
                    + ((size_t)mb * AREAS + a) * KT * 2048;

    float4 areg[2][2];
    #pragma unroll
    for (int mt = 0; mt < 2; mt++)
        #pragma unroll
        for (int h = 0; h < 2; h++)
            areg[mt][h] = *(const float4*)(Ag + (roff[h] + mt * 16) * 16 + kr * 4);

    float acc[2][4][4];
    #pragma unroll
    for (int i = 0; i < 2; i++)
        #pragma unroll
        for (int j = 0; j < 4; j++)
            #pragma unroll
            for (int k = 0; k < 4; k++) acc[i][j][k] = 0.f;

    CP_WAIT0();
    __syncthreads();

    #pragma unroll
    for (int kt = 0; kt < KT; kt++) {
        float4 bfr[4];
        #pragma unroll
        for (int nt = 0; nt < 4; nt++) {
            int n = wn * 32 + nt * 8 + qr;
            bfr[nt] = *(const float4*)(Bs + (kt * 64 + n) * 16 + kr * 4);
        }

        float4 anext[2][2];
        if (kt + 1 < KT) {
            const float* An = Ag + (kt + 1) * 2048;
            #pragma unroll
            for (int mt = 0; mt < 2; mt++)
                #pragma unroll
                for (int h = 0; h < 2; h++)
                    anext[mt][h] = *(const float4*)(An + (roff[h] + mt * 16) * 16 + kr * 4);
        }

        #pragma unroll
        for (int k8 = 0; k8 < 2; k8++) {
            #pragma unroll
            for (int mt = 0; mt < 2; mt++) {
                uint32_t a0, a1, a2, a3;
                if (k8 == 0) {
                    a0 = __float_as_uint(areg[mt][0].x);
                    a1 = __float_as_uint(areg[mt][1].x);
                    a2 = __float_as_uint(areg[mt][0].y);
                    a3 = __float_as_uint(areg[mt][1].y);
                } else {
                    a0 = __float_as_uint(areg[mt][0].z);
                    a1 = __float_as_uint(areg[mt][1].z);
                    a2 = __float_as_uint(areg[mt][0].w);
                    a3 = __float_as_uint(areg[mt][1].w);
                }
                #pragma unroll
                for (int nt = 0; nt < 4; nt++) {
                    uint32_t b0 = __float_as_uint(k8 == 0 ? bfr[nt].x : bfr[nt].z);
                    uint32_t b1 = __float_as_uint(k8 == 0 ? bfr[nt].y : bfr[nt].w);
                    asm volatile(
                        "mma.sync.aligned.m16n8k8.row.col.f32.tf32.tf32.f32 "
                        "{%0,%1,%2,%3},{%4,%5,%6,%7},{%8,%9},{%0,%1,%2,%3};"
                        : "+f"(acc[mt][nt][0]), "+f"(acc[mt][nt][1]),
                          "+f"(acc[mt][nt][2]), "+f"(acc[mt][nt][3])
                        : "r"(a0), "r"(a1), "r"(a2), "r"(a3), "r"(b0), "r"(b1));
                }
            }
        }

        if (kt + 1 < KT) {
            #pragma unroll
            for (int mt = 0; mt < 2; mt++)
                #pragma unroll
                for (int h = 0; h < 2; h++) areg[mt][h] = anext[mt][h];
        }
    }

    #pragma unroll
    for (int mt = 0; mt < 2; mt++) {
        const int r0g = chunk_row0 + mb * 128 + wm * 32 + mt * 16 + qr;
        #pragma unroll
        for (int nt = 0; nt < 4; nt++) {
            const int c  = nh * 64 + wn * 32 + nt * 8 + kr * 2;
            const float b0 = bias[a * CDIM + c];
            const float b1 = bias[a * CDIM + c + 1];
            float2 v0 = make_float2(acc[mt][nt][0] + b0, acc[mt][nt][1] + b1);
            float2 v1 = make_float2(acc[mt][nt][2] + b0, acc[mt][nt][3] + b1);
            *(float2*)(out + (size_t)r0g * OUTC + a * CDIM + c) = v0;
            *(float2*)(out + (size_t)(r0g + 8) * OUTC + a * CDIM + c) = v1;
        }
    }
}

// ---------------------------------------------------------------------------
extern "C" void kernel_launch(void* const* d_in, const int* in_sizes, int n_in,
                              void* d_out, int out_size) {
    const float* x    = (const float*)d_in[0];
    const float* W    = (const float*)d_in[1];
    const float* bias = (const float*)d_in[2];
    const int*   nr   = (const int*)  d_in[3];
    float* out = (float*)d_out;

    static bool inited = false;
    static cudaStream_t sP;
    static cudaEvent_t evFork, evP[NCHUNK], evG[NCHUNK];
    if (!inited) {
        cudaFuncSetAttribute(gemm_kernel,
                             cudaFuncAttributeMaxDynamicSharedMemorySize, SMEM_BYTES);
        cudaStreamCreateWithFlags(&sP, cudaStreamNonBlocking);
        cudaEventCreateWithFlags(&evFork, cudaEventDisableTiming);
        for (int i = 0; i < NCHUNK; i++) {
            cudaEventCreateWithFlags(&evP[i], cudaEventDisableTiming);
            cudaEventCreateWithFlags(&evG[i], cudaEventDisableTiming);
        }
        inited = true;
    }

    setup_src_kernel<<<1, 320>>>(nr);
    gperm_kernel<<<(NDIM + 255) / 256, 256>>>();
    wcvt_kernel<<<(AREAS * KT * 128 * 16 + 255) / 256, 256>>>(W);

    cudaEventRecord(evFork, 0);
    cudaStreamWaitEvent(sP, evFork, 0);

    for (int ch = 0; ch < NCHUNK; ch++) {
        const int row0 = ch * CHUNK_M;
        const int buf  = ch & 1;

        if (ch >= 2) cudaStreamWaitEvent(sP, evG[ch - 2], 0);
        permute_kernel<<<CHUNK_M / PR, 256, 0, sP>>>(x, row0, buf);
        cudaEventRecord(evP[ch], sP);

        cudaStreamWaitEvent(0, evP[ch], 0);
        gemm_kernel<<<dim3(MB_N * 2, AREAS), 256, SMEM_BYTES>>>(bias, out, row0, buf);
        cudaEventRecord(evG[ch], 0);
    }
}